// round 2
// baseline (speedup 1.0000x reference)
#include <cuda_runtime.h>
#include <math.h>

#define SEQ   4096
#define BATCH 2
#define DM    1024
#define NH    16
#define HD    64
#define LHEADS 4
#define LHD   64
#define NLAT  64
#define CHUNK 64

// ---------------- device scratch (no allocs allowed) ----------------
__device__ __align__(256) float g_qkv   [BATCH*SEQ*3*DM];   // [B,S,3D]
__device__ __align__(256) float g_local [BATCH*NH*SEQ*HD];  // [B,H,S,hd]
__device__ __align__(256) float g_pooled[BATCH*NLAT*DM];    // [B,64,D]
__device__ __align__(256) float g_rq    [BATCH*SEQ*256];    // [B,S,256]
__device__ __align__(256) float g_rkv   [BATCH*NLAT*512];   // [B,64,512]
__device__ __align__(256) float g_latout[BATCH*SEQ*256];    // [B,S,256]
__device__ __align__(256) float g_remote[BATCH*SEQ*DM];     // [B,S,D]
__device__ __align__(256) float g_mixed [BATCH*SEQ*DM];     // [B,S,D]

// ---------------- generic SGEMM: C[M,N] = A[M,K] @ B[K,N] + bias ----------------
// 128x128 block tile, BK=16, 256 threads, 8x8 per-thread microtile.
__global__ void __launch_bounds__(256) sgemm_bias(
    const float* __restrict__ A, const float* __restrict__ Bm,
    const float* __restrict__ bias, float* __restrict__ C,
    int M, int N, int K)
{
    __shared__ float As[16][128];
    __shared__ float Bs[16][128];
    int tid  = threadIdx.x;
    int brow = blockIdx.y * 128;
    int bcol = blockIdx.x * 128;
    int trow = (tid >> 4) << 3;
    int tcol = (tid & 15) << 3;

    float acc[8][8];
#pragma unroll
    for (int i = 0; i < 8; i++)
#pragma unroll
        for (int j = 0; j < 8; j++) acc[i][j] = 0.f;

    for (int k0 = 0; k0 < K; k0 += 16) {
#pragma unroll
        for (int i = 0; i < 2; i++) {
            int idx = i * 256 + tid;            // 512 float4 slots: 128 rows x 16 cols
            int r = idx >> 2;
            int c = (idx & 3) << 2;
            float4 v = *(const float4*)&A[(size_t)(brow + r) * K + k0 + c];
            As[c + 0][r] = v.x; As[c + 1][r] = v.y;
            As[c + 2][r] = v.z; As[c + 3][r] = v.w;
        }
#pragma unroll
        for (int i = 0; i < 2; i++) {
            int idx = i * 256 + tid;            // 512 float4 slots: 16 rows x 128 cols
            int r = idx >> 5;
            int c = (idx & 31) << 2;
            *(float4*)&Bs[r][c] = *(const float4*)&Bm[(size_t)(k0 + r) * N + bcol + c];
        }
        __syncthreads();
#pragma unroll
        for (int kk = 0; kk < 16; kk++) {
            float a[8], b[8];
            *(float4*)&a[0] = *(float4*)&As[kk][trow];
            *(float4*)&a[4] = *(float4*)&As[kk][trow + 4];
            *(float4*)&b[0] = *(float4*)&Bs[kk][tcol];
            *(float4*)&b[4] = *(float4*)&Bs[kk][tcol + 4];
#pragma unroll
            for (int i = 0; i < 8; i++)
#pragma unroll
                for (int j = 0; j < 8; j++)
                    acc[i][j] += a[i] * b[j];
        }
        __syncthreads();
    }

#pragma unroll
    for (int i = 0; i < 8; i++) {
        size_t row = (size_t)(brow + trow + i);
#pragma unroll
        for (int j = 0; j < 8; j += 4) {
            float4 bv = *(const float4*)&bias[bcol + tcol + j];
            float4 v;
            v.x = acc[i][j + 0] + bv.x;
            v.y = acc[i][j + 1] + bv.y;
            v.z = acc[i][j + 2] + bv.z;
            v.w = acc[i][j + 3] + bv.w;
            *(float4*)&C[row * N + bcol + tcol + j] = v;
        }
    }
}

// ---------------- local sliding-window attention ----------------
// grid: (SEQ/128, NH, BATCH), 128 threads; thread = one query position.
// Reference gathers keys per 256-block from [bstart-127, bstart+255], THEN
// applies 0 < dist <= 128. So effective key range for query q:
//   kpos in [max(0, bstart-127, q-128), q-1]  where bstart = q & ~255.
__global__ void __launch_bounds__(128) local_attn_kernel()
{
    int b  = blockIdx.z, h = blockIdx.y;
    int q0 = blockIdx.x * 128;
    int tid = threadIdx.x;
    int qpos = q0 + tid;
    const float* qkv = g_qkv + (size_t)b * SEQ * 3 * DM;

    int bstart = qpos & ~255;
    int kmin = bstart - 127;
    if (kmin < 0) kmin = 0;

    float qreg[HD];
    {
        const float* qr = qkv + (size_t)qpos * 3 * DM + h * HD;
#pragma unroll
        for (int d = 0; d < HD; d += 4) {
            float4 v = *(const float4*)(qr + d);
            qreg[d] = v.x; qreg[d + 1] = v.y; qreg[d + 2] = v.z; qreg[d + 3] = v.w;
        }
    }

    __shared__ float Ks[64][HD];
    __shared__ float Vs[64][HD];

    float m = -1e30f, ssum = 0.f;
    float acc[HD];
#pragma unroll
    for (int d = 0; d < HD; d++) acc[d] = 0.f;

    for (int t = 0; t < 4; t++) {
        int k0 = q0 - 128 + t * 64;
        __syncthreads();
#pragma unroll
        for (int i = 0; i < 8; i++) {
            int idx = i * 128 + tid;        // 1024 float4 slots: 64 rows x 16 cols
            int row = idx >> 4;
            int col = (idx & 15) << 2;
            int kpos = k0 + row;
            float4 kv = make_float4(0.f, 0.f, 0.f, 0.f);
            float4 vv = kv;
            if (kpos >= 0) {
                const float* kr = qkv + (size_t)kpos * 3 * DM + DM + h * HD + col;
                kv = *(const float4*)kr;
                vv = *(const float4*)(kr + DM);
            }
            *(float4*)&Ks[row][col] = kv;
            *(float4*)&Vs[row][col] = vv;
        }
        __syncthreads();

        for (int j = 0; j < 64; j++) {
            int kpos = k0 + j;
            int dist = qpos - kpos;
            if (dist <= 0) break;                 // keys ascending: rest are masked too
            if (dist > 128 || kpos < kmin) continue;
            float sc = 0.f;
#pragma unroll
            for (int d = 0; d < HD; d++) sc += qreg[d] * Ks[j][d];
            sc *= 0.125f;
            float p;
            if (sc > m) {
                float corr = __expf(m - sc);
                ssum *= corr;
#pragma unroll
                for (int d = 0; d < HD; d++) acc[d] *= corr;
                m = sc;
                p = 1.f;
            } else {
                p = __expf(sc - m);
            }
            ssum += p;
#pragma unroll
            for (int d = 0; d < HD; d++) acc[d] += p * Vs[j][d];
        }
    }

    float inv = (ssum > 0.f) ? (1.f / ssum) : 0.f;
    float* o = g_local + (((size_t)(b * NH + h) * SEQ) + qpos) * HD;
#pragma unroll
    for (int d = 0; d < HD; d += 4) {
        float4 v = make_float4(acc[d] * inv, acc[d + 1] * inv, acc[d + 2] * inv, acc[d + 3] * inv);
        *(float4*)(o + d) = v;
    }
}

// ---------------- pooled chunks: mean over 64-token chunks ----------------
// grid: (DM/256, NLAT, BATCH), 256 threads
__global__ void pool_kernel(const float* __restrict__ x)
{
    int d = blockIdx.x * 256 + threadIdx.x;
    int n = blockIdx.y;
    int b = blockIdx.z;
    const float* base = x + ((size_t)b * SEQ + (size_t)n * CHUNK) * DM + d;
    float s = 0.f;
#pragma unroll 8
    for (int t = 0; t < CHUNK; t++) s += base[(size_t)t * DM];
    g_pooled[((size_t)b * NLAT + n) * DM + d] = s * (1.0f / CHUNK);
}

// ---------------- latent attention ----------------
// grid: (SEQ/128, LHEADS, BATCH), 128 threads; thread = one token s.
// allowed latents: l < s/64 ; s<64 -> zero output
__global__ void __launch_bounds__(128) latent_attn_kernel()
{
    int b = blockIdx.z, h = blockIdx.y;
    int s = blockIdx.x * 128 + threadIdx.x;
    int tid = threadIdx.x;

    __shared__ float RK[NLAT][LHD];
    __shared__ float RV[NLAT][LHD];
#pragma unroll
    for (int i = 0; i < 8; i++) {
        int idx = i * 128 + tid;        // 1024 float4: 64 rows x 16 cols
        int l = idx >> 4;
        int col = (idx & 15) << 2;
        const float* kr = g_rkv + ((size_t)(b * NLAT + l)) * 512 + h * LHD + col;
        *(float4*)&RK[l][col] = *(const float4*)kr;
        *(float4*)&RV[l][col] = *(const float4*)(kr + 256);
    }
    __syncthreads();

    int cid = s >> 6;   // chunk id
    float qreg[LHD];
    {
        const float* qr = g_rq + ((size_t)(b * SEQ + s)) * 256 + h * LHD;
#pragma unroll
        for (int d = 0; d < LHD; d += 4) {
            float4 v = *(const float4*)(qr + d);
            qreg[d] = v.x; qreg[d + 1] = v.y; qreg[d + 2] = v.z; qreg[d + 3] = v.w;
        }
    }

    float m = -1e30f, ssum = 0.f;
    float acc[LHD];
#pragma unroll
    for (int d = 0; d < LHD; d++) acc[d] = 0.f;

    for (int l = 0; l < cid; l++) {
        float sc = 0.f;
#pragma unroll
        for (int d = 0; d < LHD; d++) sc += qreg[d] * RK[l][d];
        sc *= 0.125f;
        float p;
        if (sc > m) {
            float corr = __expf(m - sc);
            ssum *= corr;
#pragma unroll
            for (int d = 0; d < LHD; d++) acc[d] *= corr;
            m = sc;
            p = 1.f;
        } else {
            p = __expf(sc - m);
        }
        ssum += p;
#pragma unroll
        for (int d = 0; d < LHD; d++) acc[d] += p * RV[l][d];
    }

    float inv = (cid > 0) ? (1.f / ssum) : 0.f;
    float* o = g_latout + ((size_t)(b * SEQ + s)) * 256 + h * LHD;
#pragma unroll
    for (int d = 0; d < LHD; d += 4) {
        float4 v = make_float4(acc[d] * inv, acc[d + 1] * inv, acc[d + 2] * inv, acc[d + 3] * inv);
        *(float4*)(o + d) = v;
    }
}

// ---------------- gate + mix ----------------
// warp per (b,s,h): gate = sigmoid(local.gl + remote.gr); mixed = g*local + (1-g)*remote
__global__ void gate_mix_kernel(const float* __restrict__ gl_w, const float* __restrict__ gr_w)
{
    int w = (blockIdx.x * blockDim.x + threadIdx.x) >> 5;
    int lane = threadIdx.x & 31;
    int h = w & 15;
    int s = (w >> 4) & 4095;
    int b = w >> 16;

    const float* L = g_local + (((size_t)(b * NH + h) * SEQ) + s) * HD;
    const float* R = g_remote + ((size_t)(b * SEQ + s)) * DM + h * HD;
    float l0 = L[lane], l1 = L[lane + 32];
    float r0 = R[lane], r1 = R[lane + 32];
    float t = l0 * gl_w[lane] + l1 * gl_w[lane + 32]
            + r0 * gr_w[lane] + r1 * gr_w[lane + 32];
#pragma unroll
    for (int o = 16; o; o >>= 1) t += __shfl_xor_sync(0xffffffffu, t, o);
    float g = 1.f / (1.f + __expf(-t));
    float* Mx = g_mixed + ((size_t)(b * SEQ + s)) * DM + h * HD;
    Mx[lane]      = g * l0 + (1.f - g) * r0;
    Mx[lane + 32] = g * l1 + (1.f - g) * r1;
}

// ---------------- launch ----------------
extern "C" void kernel_launch(void* const* d_in, const int* in_sizes, int n_in,
                              void* d_out, int out_size)
{
    const float* x      = (const float*)d_in[0];
    const float* qkv_w  = (const float*)d_in[1];
    const float* qkv_b  = (const float*)d_in[2];
    const float* rq_w   = (const float*)d_in[3];
    const float* rq_b   = (const float*)d_in[4];
    const float* rkv_w  = (const float*)d_in[5];
    const float* rkv_b  = (const float*)d_in[6];
    const float* rout_w = (const float*)d_in[7];
    const float* rout_b = (const float*)d_in[8];
    const float* out_w  = (const float*)d_in[9];
    const float* out_b  = (const float*)d_in[10];
    const float* gl_w   = (const float*)d_in[11];
    const float* gr_w   = (const float*)d_in[12];
    float* out = (float*)d_out;

    float *p_qkv, *p_pooled, *p_rq, *p_rkv, *p_latout, *p_remote, *p_mixed;
    cudaGetSymbolAddress((void**)&p_qkv,    g_qkv);
    cudaGetSymbolAddress((void**)&p_pooled, g_pooled);
    cudaGetSymbolAddress((void**)&p_rq,     g_rq);
    cudaGetSymbolAddress((void**)&p_rkv,    g_rkv);
    cudaGetSymbolAddress((void**)&p_latout, g_latout);
    cudaGetSymbolAddress((void**)&p_remote, g_remote);
    cudaGetSymbolAddress((void**)&p_mixed,  g_mixed);

    const int M = BATCH * SEQ;   // 8192

    // qkv = x @ qkv_w + qkv_b
    sgemm_bias<<<dim3(3 * DM / 128, M / 128), 256>>>(x, qkv_w, qkv_b, p_qkv, M, 3 * DM, DM);
    // local attention
    local_attn_kernel<<<dim3(SEQ / 128, NH, BATCH), 128>>>();
    // pooled chunks
    pool_kernel<<<dim3(DM / 256, NLAT, BATCH), 256>>>(x);
    // rq = x @ rq_w + rq_b
    sgemm_bias<<<dim3(256 / 128, M / 128), 256>>>(x, rq_w, rq_b, p_rq, M, 256, DM);
    // rkv = pooled @ rkv_w + rkv_b      (M=128)
    sgemm_bias<<<dim3(512 / 128, 1), 256>>>(p_pooled, rkv_w, rkv_b, p_rkv, BATCH * NLAT, 512, DM);
    // latent attention
    latent_attn_kernel<<<dim3(SEQ / 128, LHEADS, BATCH), 128>>>();
    // remote = lat_out @ rout_w + rout_b
    sgemm_bias<<<dim3(DM / 128, M / 128), 256>>>(p_latout, rout_w, rout_b, p_remote, M, DM, 256);
    // gate + mix
    gate_mix_kernel<<<(BATCH * SEQ * NH) / 8, 256>>>(gl_w, gr_w);
    // out = mixed @ out_w + out_b
    sgemm_bias<<<dim3(DM / 128, M / 128), 256>>>(p_mixed, out_w, out_b, out, M, DM, DM);
}

// round 3
// speedup vs baseline: 1.8205x; 1.8205x over previous
#include <cuda_runtime.h>
#include <math.h>
#include <stdint.h>

#define SEQ   4096
#define BATCH 2
#define DM    1024
#define NH    16
#define HD    64
#define LHEADS 4
#define LHD   64
#define NLAT  64
#define CHUNK 64

// ---------------- device scratch (no allocs allowed) ----------------
__device__ __align__(256) float g_qkv   [BATCH*SEQ*3*DM];   // [B,S,3D]
__device__ __align__(256) float g_local [BATCH*NH*SEQ*HD];  // [B,H,S,hd]
__device__ __align__(256) float g_pooled[BATCH*NLAT*DM];    // [B,64,D]
__device__ __align__(256) float g_rq    [BATCH*SEQ*256];    // [B,S,256]
__device__ __align__(256) float g_rkv   [BATCH*NLAT*512];   // [B,64,512]
__device__ __align__(256) float g_latout[BATCH*SEQ*256];    // [B,S,256]
__device__ __align__(256) float g_remote[BATCH*SEQ*DM];     // [B,S,D]
__device__ __align__(256) float g_mixed [BATCH*SEQ*DM];     // [B,S,D]

__device__ __forceinline__ uint32_t f2tf32(float f) {
    uint32_t u;
    asm("cvt.rna.tf32.f32 %0, %1;" : "=r"(u) : "f"(f));
    return u;
}

#define MMA_TF32(d, a, b) \
    asm volatile("mma.sync.aligned.m16n8k8.row.col.f32.tf32.tf32.f32 " \
                 "{%0,%1,%2,%3}, {%4,%5,%6,%7}, {%8,%9}, {%0,%1,%2,%3};" \
                 : "+f"(d[0]), "+f"(d[1]), "+f"(d[2]), "+f"(d[3]) \
                 : "r"(a[0]), "r"(a[1]), "r"(a[2]), "r"(a[3]), \
                   "r"(b[0]), "r"(b[1]))

// ---------------- tf32 tensor-core GEMM: C[M,N] = A[M,K] @ B[K,N] + bias ----
// 128x128 block tile, BK=16, 256 threads (8 warps), warp tile 64x32,
// per-warp 4x4 grid of m16n8k8 mma tiles. tf32 conversion at smem store.
#define SMS 136   // smem row stride in words: (k*8 + m) mod 32 is a bijection
__global__ void __launch_bounds__(256) gemm_tf32_bias(
    const float* __restrict__ A, const float* __restrict__ Bm,
    const float* __restrict__ bias, float* __restrict__ C,
    int M, int N, int K)
{
    __shared__ uint32_t As[16][SMS];   // As[k][m]
    __shared__ uint32_t Bs[16][SMS];   // Bs[k][n]
    int tid  = threadIdx.x;
    int lane = tid & 31;
    int warp = tid >> 5;
    int brow = blockIdx.y * 128;
    int bcol = blockIdx.x * 128;
    int wM = (warp >> 2) * 64;     // warp row offset in block
    int wN = (warp & 3) * 32;      // warp col offset in block

    float acc[4][4][4];
#pragma unroll
    for (int i = 0; i < 4; i++)
#pragma unroll
        for (int j = 0; j < 4; j++)
#pragma unroll
            for (int r = 0; r < 4; r++) acc[i][j][r] = 0.f;

    for (int k0 = 0; k0 < K; k0 += 16) {
        // load A tile 128x16, transpose into As[k][m], convert to tf32
#pragma unroll
        for (int i = 0; i < 2; i++) {
            int idx = i * 256 + tid;          // 512 float4: 128 rows x 4 k-groups
            int r = idx >> 2;
            int c = (idx & 3) << 2;
            float4 v = *(const float4*)&A[(size_t)(brow + r) * K + k0 + c];
            As[c + 0][r] = f2tf32(v.x); As[c + 1][r] = f2tf32(v.y);
            As[c + 2][r] = f2tf32(v.z); As[c + 3][r] = f2tf32(v.w);
        }
        // load B tile 16x128 into Bs[k][n], convert to tf32
#pragma unroll
        for (int i = 0; i < 2; i++) {
            int idx = i * 256 + tid;          // 512 float4: 16 rows x 32 n-groups
            int r = idx >> 5;
            int c = (idx & 31) << 2;
            float4 v = *(const float4*)&Bm[(size_t)(k0 + r) * N + bcol + c];
            uint4 u;
            u.x = f2tf32(v.x); u.y = f2tf32(v.y);
            u.z = f2tf32(v.z); u.w = f2tf32(v.w);
            *(uint4*)&Bs[r][c] = u;
        }
        __syncthreads();

#pragma unroll
        for (int kk = 0; kk < 16; kk += 8) {
            uint32_t af[4][4], bf[4][2];
            int kl = kk + (lane & 3);
            int rl = lane >> 2;
#pragma unroll
            for (int mt = 0; mt < 4; mt++) {
                int m = wM + mt * 16;
                af[mt][0] = As[kl    ][m + rl    ];
                af[mt][1] = As[kl    ][m + rl + 8];
                af[mt][2] = As[kl + 4][m + rl    ];
                af[mt][3] = As[kl + 4][m + rl + 8];
            }
#pragma unroll
            for (int nt = 0; nt < 4; nt++) {
                int n = wN + nt * 8;
                bf[nt][0] = Bs[kl    ][n + rl];
                bf[nt][1] = Bs[kl + 4][n + rl];
            }
#pragma unroll
            for (int mt = 0; mt < 4; mt++)
#pragma unroll
                for (int nt = 0; nt < 4; nt++)
                    MMA_TF32(acc[mt][nt], af[mt], bf[nt]);
        }
        __syncthreads();
    }

    // epilogue: c0,c1 -> (row, col..col+1); c2,c3 -> (row+8, col..col+1)
#pragma unroll
    for (int mt = 0; mt < 4; mt++) {
        int row = brow + wM + mt * 16 + (lane >> 2);
#pragma unroll
        for (int nt = 0; nt < 4; nt++) {
            int col = bcol + wN + nt * 8 + (lane & 3) * 2;
            float b0 = bias[col], b1 = bias[col + 1];
            float2 v0 = make_float2(acc[mt][nt][0] + b0, acc[mt][nt][1] + b1);
            float2 v1 = make_float2(acc[mt][nt][2] + b0, acc[mt][nt][3] + b1);
            *(float2*)&C[(size_t)row * N + col]       = v0;
            *(float2*)&C[(size_t)(row + 8) * N + col] = v1;
        }
    }
}

// ---------------- local sliding-window attention ----------------
// grid: (SEQ/128, NH, BATCH), 128 threads; thread = one query position.
// Effective key range for query q:
//   kpos in [max(0, bstart-127, q-128), q-1]  where bstart = q & ~255.
__global__ void __launch_bounds__(128) local_attn_kernel()
{
    int b  = blockIdx.z, h = blockIdx.y;
    int q0 = blockIdx.x * 128;
    int tid = threadIdx.x;
    int qpos = q0 + tid;
    const float* qkv = g_qkv + (size_t)b * SEQ * 3 * DM;

    int bstart = qpos & ~255;
    int kmin = bstart - 127;
    if (kmin < 0) kmin = 0;

    float qreg[HD];
    {
        const float* qr = qkv + (size_t)qpos * 3 * DM + h * HD;
#pragma unroll
        for (int d = 0; d < HD; d += 4) {
            float4 v = *(const float4*)(qr + d);
            qreg[d] = v.x; qreg[d + 1] = v.y; qreg[d + 2] = v.z; qreg[d + 3] = v.w;
        }
    }

    __shared__ float Ks[64][HD];
    __shared__ float Vs[64][HD];

    float m = -1e30f, ssum = 0.f;
    float acc[HD];
#pragma unroll
    for (int d = 0; d < HD; d++) acc[d] = 0.f;

    for (int t = 0; t < 4; t++) {
        int k0 = q0 - 128 + t * 64;
        __syncthreads();
#pragma unroll
        for (int i = 0; i < 8; i++) {
            int idx = i * 128 + tid;
            int row = idx >> 4;
            int col = (idx & 15) << 2;
            int kpos = k0 + row;
            float4 kv = make_float4(0.f, 0.f, 0.f, 0.f);
            float4 vv = kv;
            if (kpos >= 0) {
                const float* kr = qkv + (size_t)kpos * 3 * DM + DM + h * HD + col;
                kv = *(const float4*)kr;
                vv = *(const float4*)(kr + DM);
            }
            *(float4*)&Ks[row][col] = kv;
            *(float4*)&Vs[row][col] = vv;
        }
        __syncthreads();

        for (int j = 0; j < 64; j++) {
            int kpos = k0 + j;
            int dist = qpos - kpos;
            if (dist <= 0) break;
            if (dist > 128 || kpos < kmin) continue;
            float sc = 0.f;
#pragma unroll
            for (int d = 0; d < HD; d++) sc += qreg[d] * Ks[j][d];
            sc *= 0.125f;
            float p;
            if (sc > m) {
                float corr = __expf(m - sc);
                ssum *= corr;
#pragma unroll
                for (int d = 0; d < HD; d++) acc[d] *= corr;
                m = sc;
                p = 1.f;
            } else {
                p = __expf(sc - m);
            }
            ssum += p;
#pragma unroll
            for (int d = 0; d < HD; d++) acc[d] += p * Vs[j][d];
        }
    }

    float inv = (ssum > 0.f) ? (1.f / ssum) : 0.f;
    float* o = g_local + (((size_t)(b * NH + h) * SEQ) + qpos) * HD;
#pragma unroll
    for (int d = 0; d < HD; d += 4) {
        float4 v = make_float4(acc[d] * inv, acc[d + 1] * inv, acc[d + 2] * inv, acc[d + 3] * inv);
        *(float4*)(o + d) = v;
    }
}

// ---------------- pooled chunks: mean over 64-token chunks ----------------
__global__ void pool_kernel(const float* __restrict__ x)
{
    int d = blockIdx.x * 256 + threadIdx.x;
    int n = blockIdx.y;
    int b = blockIdx.z;
    const float* base = x + ((size_t)b * SEQ + (size_t)n * CHUNK) * DM + d;
    float s = 0.f;
#pragma unroll 8
    for (int t = 0; t < CHUNK; t++) s += base[(size_t)t * DM];
    g_pooled[((size_t)b * NLAT + n) * DM + d] = s * (1.0f / CHUNK);
}

// ---------------- latent attention ----------------
__global__ void __launch_bounds__(128) latent_attn_kernel()
{
    int b = blockIdx.z, h = blockIdx.y;
    int s = blockIdx.x * 128 + threadIdx.x;
    int tid = threadIdx.x;

    __shared__ float RK[NLAT][LHD];
    __shared__ float RV[NLAT][LHD];
#pragma unroll
    for (int i = 0; i < 8; i++) {
        int idx = i * 128 + tid;
        int l = idx >> 4;
        int col = (idx & 15) << 2;
        const float* kr = g_rkv + ((size_t)(b * NLAT + l)) * 512 + h * LHD + col;
        *(float4*)&RK[l][col] = *(const float4*)kr;
        *(float4*)&RV[l][col] = *(const float4*)(kr + 256);
    }
    __syncthreads();

    int cid = s >> 6;
    float qreg[LHD];
    {
        const float* qr = g_rq + ((size_t)(b * SEQ + s)) * 256 + h * LHD;
#pragma unroll
        for (int d = 0; d < LHD; d += 4) {
            float4 v = *(const float4*)(qr + d);
            qreg[d] = v.x; qreg[d + 1] = v.y; qreg[d + 2] = v.z; qreg[d + 3] = v.w;
        }
    }

    float m = -1e30f, ssum = 0.f;
    float acc[LHD];
#pragma unroll
    for (int d = 0; d < LHD; d++) acc[d] = 0.f;

    for (int l = 0; l < cid; l++) {
        float sc = 0.f;
#pragma unroll
        for (int d = 0; d < LHD; d++) sc += qreg[d] * RK[l][d];
        sc *= 0.125f;
        float p;
        if (sc > m) {
            float corr = __expf(m - sc);
            ssum *= corr;
#pragma unroll
            for (int d = 0; d < LHD; d++) acc[d] *= corr;
            m = sc;
            p = 1.f;
        } else {
            p = __expf(sc - m);
        }
        ssum += p;
#pragma unroll
        for (int d = 0; d < LHD; d++) acc[d] += p * RV[l][d];
    }

    float inv = (cid > 0) ? (1.f / ssum) : 0.f;
    float* o = g_latout + ((size_t)(b * SEQ + s)) * 256 + h * LHD;
#pragma unroll
    for (int d = 0; d < LHD; d += 4) {
        float4 v = make_float4(acc[d] * inv, acc[d + 1] * inv, acc[d + 2] * inv, acc[d + 3] * inv);
        *(float4*)(o + d) = v;
    }
}

// ---------------- gate + mix ----------------
__global__ void gate_mix_kernel(const float* __restrict__ gl_w, const float* __restrict__ gr_w)
{
    int w = (blockIdx.x * blockDim.x + threadIdx.x) >> 5;
    int lane = threadIdx.x & 31;
    int h = w & 15;
    int s = (w >> 4) & 4095;
    int b = w >> 16;

    const float* L = g_local + (((size_t)(b * NH + h) * SEQ) + s) * HD;
    const float* R = g_remote + ((size_t)(b * SEQ + s)) * DM + h * HD;
    float l0 = L[lane], l1 = L[lane + 32];
    float r0 = R[lane], r1 = R[lane + 32];
    float t = l0 * gl_w[lane] + l1 * gl_w[lane + 32]
            + r0 * gr_w[lane] + r1 * gr_w[lane + 32];
#pragma unroll
    for (int o = 16; o; o >>= 1) t += __shfl_xor_sync(0xffffffffu, t, o);
    float g = 1.f / (1.f + __expf(-t));
    float* Mx = g_mixed + ((size_t)(b * SEQ + s)) * DM + h * HD;
    Mx[lane]      = g * l0 + (1.f - g) * r0;
    Mx[lane + 32] = g * l1 + (1.f - g) * r1;
}

// ---------------- launch ----------------
extern "C" void kernel_launch(void* const* d_in, const int* in_sizes, int n_in,
                              void* d_out, int out_size)
{
    const float* x      = (const float*)d_in[0];
    const float* qkv_w  = (const float*)d_in[1];
    const float* qkv_b  = (const float*)d_in[2];
    const float* rq_w   = (const float*)d_in[3];
    const float* rq_b   = (const float*)d_in[4];
    const float* rkv_w  = (const float*)d_in[5];
    const float* rkv_b  = (const float*)d_in[6];
    const float* rout_w = (const float*)d_in[7];
    const float* rout_b = (const float*)d_in[8];
    const float* out_w  = (const float*)d_in[9];
    const float* out_b  = (const float*)d_in[10];
    const float* gl_w   = (const float*)d_in[11];
    const float* gr_w   = (const float*)d_in[12];
    float* out = (float*)d_out;

    float *p_qkv, *p_pooled, *p_rq, *p_rkv, *p_latout, *p_remote, *p_mixed;
    cudaGetSymbolAddress((void**)&p_qkv,    g_qkv);
    cudaGetSymbolAddress((void**)&p_pooled, g_pooled);
    cudaGetSymbolAddress((void**)&p_rq,     g_rq);
    cudaGetSymbolAddress((void**)&p_rkv,    g_rkv);
    cudaGetSymbolAddress((void**)&p_latout, g_latout);
    cudaGetSymbolAddress((void**)&p_remote, g_remote);
    cudaGetSymbolAddress((void**)&p_mixed,  g_mixed);

    const int M = BATCH * SEQ;   // 8192

    // qkv = x @ qkv_w + qkv_b
    gemm_tf32_bias<<<dim3(3 * DM / 128, M / 128), 256>>>(x, qkv_w, qkv_b, p_qkv, M, 3 * DM, DM);
    // local attention
    local_attn_kernel<<<dim3(SEQ / 128, NH, BATCH), 128>>>();
    // pooled chunks
    pool_kernel<<<dim3(DM / 256, NLAT, BATCH), 256>>>(x);
    // rq = x @ rq_w + rq_b
    gemm_tf32_bias<<<dim3(256 / 128, M / 128), 256>>>(x, rq_w, rq_b, p_rq, M, 256, DM);
    // rkv = pooled @ rkv_w + rkv_b      (M=128)
    gemm_tf32_bias<<<dim3(512 / 128, 1), 256>>>(p_pooled, rkv_w, rkv_b, p_rkv, BATCH * NLAT, 512, DM);
    // latent attention
    latent_attn_kernel<<<dim3(SEQ / 128, LHEADS, BATCH), 128>>>();
    // remote = lat_out @ rout_w + rout_b
    gemm_tf32_bias<<<dim3(DM / 128, M / 128), 256>>>(p_latout, rout_w, rout_b, p_remote, M, DM, 256);
    // gate + mix
    gate_mix_kernel<<<(BATCH * SEQ * NH) / 8, 256>>>(gl_w, gr_w);
    // out = mixed @ out_w + out_b
    gemm_tf32_bias<<<dim3(DM / 128, M / 128), 256>>>(p_mixed, out_w, out_b, out, M, DM, DM);
}